// round 14
// baseline (speedup 1.0000x reference)
#include <cuda_runtime.h>

// Fixed problem shape
#define NB 2048
#define ND 16384
#define RSPLIT 64
#define ROWS_PER (NB / RSPLIT)            // 32 rows per partial block
#define FIN_BLOCKS (ND / (256 * 2))       // 32 blocks, 2 cols/thread

// Scratch (__device__ globals; zero-init, no allocation allowed)
__device__ float g_psum[RSPLIT * ND];
__device__ float g_psq [RSPLIT * ND];
__device__ float g_nmean[ND];
__device__ float g_nvar [ND];
__device__ float g_inv  [ND];             // 1 / (new_var + addend)
__device__ float g_varpart[FIN_BLOCKS];
__device__ int   g_fcnt;                  // zero-init; self-resetting

// ---------------------------------------------------------------------------
// Pass 1: per-(rowchunk, column) partial sum / sumsq.
// grid = (ND/1024, RSPLIT), block = 256, 4 cols/thread, 32 rows/block.
// (Measured 23.5us, 74% DRAM — at the pure-read ceiling.)
// ---------------------------------------------------------------------------
__global__ void __launch_bounds__(256) k_colstats_partial(const float* __restrict__ h) {
    const int c  = (blockIdx.x * 256 + threadIdx.x) * 4;
    const int r0 = blockIdx.y * ROWS_PER;
    float4 s = make_float4(0.f, 0.f, 0.f, 0.f);
    float4 q = make_float4(0.f, 0.f, 0.f, 0.f);
    const float4* hp = reinterpret_cast<const float4*>(h + (size_t)r0 * ND + c);
    const size_t stride4 = ND / 4;
#pragma unroll 8
    for (int r = 0; r < ROWS_PER; ++r) {
        float4 v = __ldcs(&hp[(size_t)r * stride4]);
        s.x += v.x;       s.y += v.y;       s.z += v.z;       s.w += v.w;
        q.x += v.x * v.x; q.y += v.y * v.y; q.z += v.z * v.z; q.w += v.w * v.w;
    }
    *reinterpret_cast<float4*>(g_psum + (size_t)blockIdx.y * ND + c) = s;
    *reinterpret_cast<float4*>(g_psq  + (size_t)blockIdx.y * ND + c) = q;
}

// ---------------------------------------------------------------------------
// Pass 2 (finish + addend + inv): finish stats -> new_mean, new_var; the LAST
// block (arrival-ordered counter, proven pattern) reduces the 32 varparts to
// addend and writes the entire inv array itself (16 float4/thread, L2-hot).
// No cross-block spin anywhere. grid = 32, block = 256, 2 cols/thread.
// ---------------------------------------------------------------------------
__global__ void __launch_bounds__(256) k_colstats_finish(const float* __restrict__ hmean,
                                                         const float* __restrict__ hvar) {
    const int c = (blockIdx.x * 256 + threadIdx.x) * 2;
    float2 s = make_float2(0.f, 0.f);
    float2 q = make_float2(0.f, 0.f);
#pragma unroll 8
    for (int i = 0; i < RSPLIT; ++i) {
        float2 a = *reinterpret_cast<const float2*>(g_psum + (size_t)i * ND + c);
        float2 b = *reinterpret_cast<const float2*>(g_psq  + (size_t)i * ND + c);
        s.x += a.x; s.y += a.y;
        q.x += b.x; q.y += b.y;
    }
    const float invB    = 1.0f / (float)NB;
    const float U       = 10.0f;
    const float inv11   = 1.0f / 11.0f;
    const float inv1p1  = 1.0f / 1.1f;
    const float invDen  = 1.0f / (U + 1.0f - invB);
    const float coefOld = U - invB;

    float2 hm = *reinterpret_cast<const float2*>(hmean + c);
    float2 hv = *reinterpret_cast<const float2*>(hvar  + c);

    float2 nm, nv;
    {
        float mu, var, d;
        mu = s.x * invB; var = q.x * invB - mu * mu; d = mu - hm.x;
        nv.x = (hv.x * coefOld + var + d * d * inv1p1) * invDen;
        nm.x = (hm.x * U + mu) * inv11;
        mu = s.y * invB; var = q.y * invB - mu * mu; d = mu - hm.y;
        nv.y = (hv.y * coefOld + var + d * d * inv1p1) * invDen;
        nm.y = (hm.y * U + mu) * inv11;
    }
    *reinterpret_cast<float2*>(g_nmean + c) = nm;
    *reinterpret_cast<float2*>(g_nvar  + c) = nv;

    __shared__ float sred[256];
    sred[threadIdx.x] = nv.x + nv.y;
    __syncthreads();
    for (int off = 128; off > 0; off >>= 1) {
        if (threadIdx.x < off) sred[threadIdx.x] += sred[threadIdx.x + off];
        __syncthreads();
    }

    __shared__ int is_last;
    if (threadIdx.x == 0) {
        g_varpart[blockIdx.x] = sred[0];
        __threadfence();                      // varpart + nvar visible
        int old = atomicAdd(&g_fcnt, 1);
        is_last = (old == FIN_BLOCKS - 1) ? 1 : 0;
    }
    __syncthreads();

    if (is_last) {
        // addend = mean(new_var)/100 (deterministic fixed tree)
        __shared__ float s_add;
        if (threadIdx.x < 32) {
            __threadfence();                  // acquire side
            float v = g_varpart[threadIdx.x]; // FIN_BLOCKS == 32
#pragma unroll
            for (int off = 16; off > 0; off >>= 1)
                v += __shfl_down_sync(0xFFFFFFFFu, v, off);
            if (threadIdx.x == 0) s_add = (v / (float)ND) * 0.01f;
        }
        __syncthreads();
        const float a = s_add;

        // whole inv array from this block: 4096 float4, 16 per thread (L2-hot)
        const float4* nv4 = reinterpret_cast<const float4*>(g_nvar);
        float4*       iv4 = reinterpret_cast<float4*>(g_inv);
#pragma unroll
        for (int j = threadIdx.x; j < ND / 4; j += 256) {
            float4 v = __ldcs(&nv4[j]);
            float4 iv;
            iv.x = 1.0f / (v.x + a);
            iv.y = 1.0f / (v.y + a);
            iv.z = 1.0f / (v.z + a);
            iv.w = 1.0f / (v.w + a);
            iv4[j] = iv;
        }
        __syncthreads();
        if (threadIdx.x == 0) g_fcnt = 0;     // reset for next graph replay
    }
}

// ---------------------------------------------------------------------------
// Pass 3: per-row copy + argmax of (h-nm)^2 * inv + winner fixup.
// grid = NB, block = 256, one row per block. Best-measured hot loop (43.0us):
// 2-way float4 ILP, strict-> compare chain (ascending columns per thread),
// __ldcs h reads, __stcs out writes, lowest-index tie-break in block reduce
// (jnp.argmax semantics). UNCHANGED from R11/R13.
// ---------------------------------------------------------------------------
__global__ void __launch_bounds__(256, 6) k_punish(const float* __restrict__ h,
                                                   float* __restrict__ out) {
    const int row = blockIdx.x;
    const int tid = threadIdx.x;

    const float4* hrow = reinterpret_cast<const float4*>(h   + (size_t)row * ND);
    float4*       orow = reinterpret_cast<float4*>      (out + (size_t)row * ND);
    const float4* m4p  = reinterpret_cast<const float4*>(g_nmean);
    const float4* i4p  = reinterpret_cast<const float4*>(g_inv);

    float best = -1.0f;
    int   bidx = 0;

#pragma unroll
    for (int it = 0; it < ND / (256 * 4 * 2); ++it) {     // 8 steps, 2 chunks each
        const int j0 = it * 512 + tid;
        const int j1 = j0 + 256;

        float4 h0 = __ldcs(&hrow[j0]);
        float4 h1 = __ldcs(&hrow[j1]);
        float4 m0 = __ldg(&m4p[j0]);
        float4 m1 = __ldg(&m4p[j1]);
        float4 v0 = __ldg(&i4p[j0]);
        float4 v1 = __ldg(&i4p[j1]);

        __stcs(&orow[j0], h0);
        __stcs(&orow[j1], h1);

        const int c0 = j0 * 4, c1 = j1 * 4;
        float d, sc;
        d = h0.x - m0.x; sc = d * d * v0.x; if (sc > best) { best = sc; bidx = c0;     }
        d = h0.y - m0.y; sc = d * d * v0.y; if (sc > best) { best = sc; bidx = c0 + 1; }
        d = h0.z - m0.z; sc = d * d * v0.z; if (sc > best) { best = sc; bidx = c0 + 2; }
        d = h0.w - m0.w; sc = d * d * v0.w; if (sc > best) { best = sc; bidx = c0 + 3; }
        d = h1.x - m1.x; sc = d * d * v1.x; if (sc > best) { best = sc; bidx = c1;     }
        d = h1.y - m1.y; sc = d * d * v1.y; if (sc > best) { best = sc; bidx = c1 + 1; }
        d = h1.z - m1.z; sc = d * d * v1.z; if (sc > best) { best = sc; bidx = c1 + 2; }
        d = h1.w - m1.w; sc = d * d * v1.w; if (sc > best) { best = sc; bidx = c1 + 3; }
    }

    __shared__ float sbest[256];
    __shared__ int   sidx[256];
    sbest[tid] = best;
    sidx[tid]  = bidx;
    __syncthreads();
    for (int off = 128; off > 0; off >>= 1) {
        if (tid < off) {
            float ob = sbest[tid + off];
            int   oi = sidx[tid + off];
            if (ob > sbest[tid] || (ob == sbest[tid] && oi < sidx[tid])) {
                sbest[tid] = ob;
                sidx[tid]  = oi;
            }
        }
        __syncthreads();
    }
    if (tid == 0) {
        int w = sidx[0];
        out[(size_t)row * ND + w] = g_nmean[w];
    }
}

// ---------------------------------------------------------------------------
extern "C" void kernel_launch(void* const* d_in, const int* in_sizes, int n_in,
                              void* d_out, int out_size) {
    const float* h     = (const float*)d_in[0];
    const float* hmean = (const float*)d_in[1];
    const float* hvar  = (const float*)d_in[2];
    float* out = (float*)d_out;
    (void)in_sizes; (void)n_in; (void)out_size;

    dim3 g1(ND / (256 * 4), RSPLIT);
    k_colstats_partial<<<g1, 256>>>(h);
    k_colstats_finish<<<FIN_BLOCKS, 256>>>(hmean, hvar);
    k_punish<<<NB, 256>>>(h, out);
}

// round 15
// speedup vs baseline: 1.0842x; 1.0842x over previous
#include <cuda_runtime.h>

// Fixed problem shape
#define NB 2048
#define ND 16384
#define RSPLIT 64
#define ROWS_PER (NB / RSPLIT)            // 32 rows per partial block
#define FIN_BLOCKS (ND / (256 * 2))       // 32 blocks, 2 cols/thread
#define SI_BLOCKS 64                      // fused scalar+inv: 64 * 256 = 16384

// Scratch (__device__ globals; no allocation allowed)
__device__ float g_psum[RSPLIT * ND];
__device__ float g_psq [RSPLIT * ND];
__device__ float g_nmean[ND];
__device__ float g_nvar [ND];
__device__ float g_inv  [ND];             // 1 / (new_var + addend)
__device__ float g_varpart[FIN_BLOCKS];

// ---------------------------------------------------------------------------
// Pass 1: per-(rowchunk, column) partial sum / sumsq.
// grid = (ND/1024, RSPLIT), block = 256, 4 cols/thread, 32 rows/block.
// Measured 23.5us @ 74% DRAM (pure-read ceiling), reproduced 5x.
// ---------------------------------------------------------------------------
__global__ void __launch_bounds__(256) k_colstats_partial(const float* __restrict__ h) {
    const int c  = (blockIdx.x * 256 + threadIdx.x) * 4;
    const int r0 = blockIdx.y * ROWS_PER;
    float4 s = make_float4(0.f, 0.f, 0.f, 0.f);
    float4 q = make_float4(0.f, 0.f, 0.f, 0.f);
    const float4* hp = reinterpret_cast<const float4*>(h + (size_t)r0 * ND + c);
    const size_t stride4 = ND / 4;
#pragma unroll 8
    for (int r = 0; r < ROWS_PER; ++r) {
        float4 v = __ldcs(&hp[(size_t)r * stride4]);
        s.x += v.x;       s.y += v.y;       s.z += v.z;       s.w += v.w;
        q.x += v.x * v.x; q.y += v.y * v.y; q.z += v.z * v.z; q.w += v.w * v.w;
    }
    *reinterpret_cast<float4*>(g_psum + (size_t)blockIdx.y * ND + c) = s;
    *reinterpret_cast<float4*>(g_psq  + (size_t)blockIdx.y * ND + c) = q;
}

// ---------------------------------------------------------------------------
// Pass 2: finish stats -> new_mean, new_var; partial sum(new_var).
// grid = FIN_BLOCKS (32), block = 256, 2 cols/thread. Measured ~3us.
// NOTE: do NOT fuse tail work here — three independent experiments (spin
// fusion x2, last-block inv) each cost ~6us vs the separate kernel below.
// ---------------------------------------------------------------------------
__global__ void __launch_bounds__(256) k_colstats_finish(const float* __restrict__ hmean,
                                                         const float* __restrict__ hvar) {
    const int c = (blockIdx.x * 256 + threadIdx.x) * 2;
    float2 s = make_float2(0.f, 0.f);
    float2 q = make_float2(0.f, 0.f);
#pragma unroll 8
    for (int i = 0; i < RSPLIT; ++i) {
        float2 a = *reinterpret_cast<const float2*>(g_psum + (size_t)i * ND + c);
        float2 b = *reinterpret_cast<const float2*>(g_psq  + (size_t)i * ND + c);
        s.x += a.x; s.y += a.y;
        q.x += b.x; q.y += b.y;
    }
    const float invB    = 1.0f / (float)NB;
    const float U       = 10.0f;
    const float inv11   = 1.0f / 11.0f;
    const float inv1p1  = 1.0f / 1.1f;
    const float invDen  = 1.0f / (U + 1.0f - invB);
    const float coefOld = U - invB;

    float2 hm = *reinterpret_cast<const float2*>(hmean + c);
    float2 hv = *reinterpret_cast<const float2*>(hvar  + c);

    float2 nm, nv;
    {
        float mu, var, d;
        mu = s.x * invB; var = q.x * invB - mu * mu; d = mu - hm.x;
        nv.x = (hv.x * coefOld + var + d * d * inv1p1) * invDen;
        nm.x = (hm.x * U + mu) * inv11;
        mu = s.y * invB; var = q.y * invB - mu * mu; d = mu - hm.y;
        nv.y = (hv.y * coefOld + var + d * d * inv1p1) * invDen;
        nm.y = (hm.y * U + mu) * inv11;
    }
    *reinterpret_cast<float2*>(g_nmean + c) = nm;
    *reinterpret_cast<float2*>(g_nvar  + c) = nv;

    __shared__ float sred[256];
    sred[threadIdx.x] = nv.x + nv.y;
    __syncthreads();
    for (int off = 128; off > 0; off >>= 1) {
        if (threadIdx.x < off) sred[threadIdx.x] += sred[threadIdx.x + off];
        __syncthreads();
    }
    if (threadIdx.x == 0) g_varpart[blockIdx.x] = sred[0];
}

// ---------------------------------------------------------------------------
// Pass 3 (fused scalar + inv): every block redundantly reduces the 32 L2-hot
// varpart values to addend, then writes its slice of inv = 1/(nvar+a).
// grid = SI_BLOCKS (64), block = 256, 1 col/thread. Measured ~2.5us.
// ---------------------------------------------------------------------------
__global__ void __launch_bounds__(256) k_scalar_inv() {
    __shared__ float s_add;
    if (threadIdx.x < 32) {
        float v = g_varpart[threadIdx.x];   // FIN_BLOCKS == 32
#pragma unroll
        for (int off = 16; off > 0; off >>= 1)
            v += __shfl_down_sync(0xFFFFFFFFu, v, off);
        if (threadIdx.x == 0) s_add = (v / (float)ND) * 0.01f;
    }
    __syncthreads();
    const float a = s_add;
    const int c = blockIdx.x * 256 + threadIdx.x;
    g_inv[c] = 1.0f / (g_nvar[c] + a);
}

// ---------------------------------------------------------------------------
// Pass 4: per-row copy + argmax of (h-nm)^2 * inv + winner fixup.
// grid = NB, block = 256, one row per block. Best-measured hot loop
// (43.0us = 5.95TB/s logical, at the stream ceiling): 2-way float4 ILP,
// strict-> compare chain (ascending columns per thread -> first-match wins),
// __ldcs h reads, __stcs out writes, lowest-index tie-break in the block
// reduction — exact jnp.argmax semantics.
// ---------------------------------------------------------------------------
__global__ void __launch_bounds__(256, 6) k_punish(const float* __restrict__ h,
                                                   float* __restrict__ out) {
    const int row = blockIdx.x;
    const int tid = threadIdx.x;

    const float4* hrow = reinterpret_cast<const float4*>(h   + (size_t)row * ND);
    float4*       orow = reinterpret_cast<float4*>      (out + (size_t)row * ND);
    const float4* m4p  = reinterpret_cast<const float4*>(g_nmean);
    const float4* i4p  = reinterpret_cast<const float4*>(g_inv);

    float best = -1.0f;
    int   bidx = 0;

#pragma unroll
    for (int it = 0; it < ND / (256 * 4 * 2); ++it) {     // 8 steps, 2 chunks each
        const int j0 = it * 512 + tid;
        const int j1 = j0 + 256;

        float4 h0 = __ldcs(&hrow[j0]);
        float4 h1 = __ldcs(&hrow[j1]);
        float4 m0 = __ldg(&m4p[j0]);
        float4 m1 = __ldg(&m4p[j1]);
        float4 v0 = __ldg(&i4p[j0]);
        float4 v1 = __ldg(&i4p[j1]);

        __stcs(&orow[j0], h0);
        __stcs(&orow[j1], h1);

        const int c0 = j0 * 4, c1 = j1 * 4;
        float d, sc;
        d = h0.x - m0.x; sc = d * d * v0.x; if (sc > best) { best = sc; bidx = c0;     }
        d = h0.y - m0.y; sc = d * d * v0.y; if (sc > best) { best = sc; bidx = c0 + 1; }
        d = h0.z - m0.z; sc = d * d * v0.z; if (sc > best) { best = sc; bidx = c0 + 2; }
        d = h0.w - m0.w; sc = d * d * v0.w; if (sc > best) { best = sc; bidx = c0 + 3; }
        d = h1.x - m1.x; sc = d * d * v1.x; if (sc > best) { best = sc; bidx = c1;     }
        d = h1.y - m1.y; sc = d * d * v1.y; if (sc > best) { best = sc; bidx = c1 + 1; }
        d = h1.z - m1.z; sc = d * d * v1.z; if (sc > best) { best = sc; bidx = c1 + 2; }
        d = h1.w - m1.w; sc = d * d * v1.w; if (sc > best) { best = sc; bidx = c1 + 3; }
    }

    __shared__ float sbest[256];
    __shared__ int   sidx[256];
    sbest[tid] = best;
    sidx[tid]  = bidx;
    __syncthreads();
    for (int off = 128; off > 0; off >>= 1) {
        if (tid < off) {
            float ob = sbest[tid + off];
            int   oi = sidx[tid + off];
            if (ob > sbest[tid] || (ob == sbest[tid] && oi < sidx[tid])) {
                sbest[tid] = ob;
                sidx[tid]  = oi;
            }
        }
        __syncthreads();
    }
    if (tid == 0) {
        int w = sidx[0];
        out[(size_t)row * ND + w] = g_nmean[w];
    }
}

// ---------------------------------------------------------------------------
extern "C" void kernel_launch(void* const* d_in, const int* in_sizes, int n_in,
                              void* d_out, int out_size) {
    const float* h     = (const float*)d_in[0];
    const float* hmean = (const float*)d_in[1];
    const float* hvar  = (const float*)d_in[2];
    float* out = (float*)d_out;
    (void)in_sizes; (void)n_in; (void)out_size;

    dim3 g1(ND / (256 * 4), RSPLIT);
    k_colstats_partial<<<g1, 256>>>(h);
    k_colstats_finish<<<FIN_BLOCKS, 256>>>(hmean, hvar);
    k_scalar_inv<<<SI_BLOCKS, 256>>>();
    k_punish<<<NB, 256>>>(h, out);
}